// round 12
// baseline (speedup 1.0000x reference)
#include <cuda_runtime.h>
#include <cstdint>

#define BATCH 4
#define SEQ   2048
#define CH    1024

#define BM 128
#define BN 128
#define BK 32
#define NTHR 256
#define PAD 48              // floats per smem row (32 data + 16 pad) -> conflict-free float4 frags
#define ASZ_F (BM * PAD)    // 6144 floats per A stage
#define BSZ_F (BN * PAD)    // 6144 floats per B stage

// ---------------- scratch (device globals; allocation-free) ----------------
__device__ float g_Q [BATCH*SEQ*CH];            // 32 MB (tf32-rounded Q)
__device__ float g_Kb[BATCH*SEQ*CH];            // 32 MB (tf32-rounded K)
__device__ float g_Vt[BATCH*SEQ*CH];            // 32 MB (V^T per batch [CH, SEQ], rounded)
__device__ float g_S [(size_t)BATCH*SEQ*SEQ];   // 64 MB scores / probs
__device__ float g_XR[BATCH*SEQ*CH];            // 32 MB rounded x (later rounded residual)
__device__ float g_CR[BATCH*SEQ*CH];            // 32 MB rounded content_embeddings
__device__ float g_WR[4*CH*CH];                 // 16 MB rounded Wq,Wk,Wv,Wo

// ---------------- helpers ----------------
__device__ __forceinline__ uint32_t smem_u32(const void* p){
    uint32_t a;
    asm("{ .reg .u64 t; cvta.to.shared.u64 t, %1; cvt.u32.u64 %0, t; }" : "=r"(a) : "l"(p));
    return a;
}
__device__ __forceinline__ void cp16(uint32_t dst, const void* src){
    asm volatile("cp.async.cg.shared.global [%0], [%1], 16;" :: "r"(dst), "l"(src));
}
__device__ __forceinline__ void lds128(float4& v, uint32_t a){
    asm volatile("ld.shared.v4.f32 {%0,%1,%2,%3}, [%4];"
                 : "=f"(v.x), "=f"(v.y), "=f"(v.z), "=f"(v.w) : "r"(a));
}
__device__ __forceinline__ float rn_tf32(float x){
    uint32_t u; asm("cvt.rna.tf32.f32 %0, %1;" : "=r"(u) : "f"(x));
    return __uint_as_float(u);
}
__device__ __forceinline__ void mma4(float* d, float a0, float a1, float a2, float a3,
                                     float b0, float b1){
    asm volatile(
        "mma.sync.aligned.m16n8k8.row.col.f32.tf32.tf32.f32 "
        "{%0,%1,%2,%3}, {%4,%5,%6,%7}, {%8,%9}, {%0,%1,%2,%3};"
        : "+f"(d[0]), "+f"(d[1]), "+f"(d[2]), "+f"(d[3])
        : "r"(__float_as_uint(a0)), "r"(__float_as_uint(a1)),
          "r"(__float_as_uint(a2)), "r"(__float_as_uint(a3)),
          "r"(__float_as_uint(b0)), "r"(__float_as_uint(b1)));
}

// ---------------- tf32 tensor-core NT GEMM ----------------
// C[m,n] = sum_k A[m,k]*B[n,k] (+ bias[n]) (+ resid[m,n]); A:[M,K], B:[N,K] row-major.
// 128x128 block tile, 64x32 warp tiles (8 warps, 2x4), BK=32, 2-stage cp.async,
// 2 CTAs per SM. All SMEM fragment addresses are a single per-thread base +
// compile-time immediates.
// 4-wide k-slot permutation: within each 16-k pair, thread lr owns physical
// k = 4lr..4lr+3 via ONE LDS.128. MMA group 0 uses (.x,.y) = phys (4lr,4lr+1)
// at slots (lr,lr+4); group 1 uses (.z,.w) = phys (4lr+2,4lr+3). A and B use
// the same map, so each MMA contracts matching k; the two groups together
// cover all 16 k exactly once (order-invariant sum -> identical results).
__global__ __launch_bounds__(NTHR, 2) void gemm_tf32(
    const float* __restrict__ A, const float* __restrict__ Bm,
    const float* __restrict__ bias, const float* __restrict__ Rm,
    float* __restrict__ Cm,
    int M, int N, int K,
    long long az, long long bz, long long cz, int round_out)
{
    extern __shared__ float sm[];
    const uint32_t asb = smem_u32(sm);                 // A stages: [2][BM][PAD]
    const uint32_t bsb = asb + 2 * ASZ_F * 4;          // B stages: [2][BN][PAD]

    const int tid  = threadIdx.x;
    const int wid  = tid >> 5;
    const int lane = tid & 31;
    const int lq   = lane >> 2;   // 0..7
    const int lr   = lane & 3;    // 0..3

    const int z = blockIdx.z;
    const float* Ab = A  + (long long)z * az;
    const float* Bb = Bm + (long long)z * bz;
    float*       Cb = Cm + (long long)z * cz;
    const float* Rb = Rm ? (Rm + (long long)z * cz) : nullptr;
    const int m0 = blockIdx.y * BM;
    const int n0 = blockIdx.x * BN;
    const int KT = K / BK;

    const int warp_m = (wid & 1) * 64;    // 2 warps along M
    const int warp_n = (wid >> 1) * 32;   // 4 warps along N

    float acc[4][4][4];
    #pragma unroll
    for (int i = 0; i < 4; i++)
        #pragma unroll
        for (int j = 0; j < 4; j++)
            #pragma unroll
            for (int r = 0; r < 4; r++) acc[i][j][r] = 0.0f;

    // ---- persistent loader state: 1024 16B-chunks per operand, 4/thread each,
    //      rows lrow + it*32, advanced by BK floats per stage ----
    const int lrow = tid >> 3, lcol = tid & 7;
    const float* agp = Ab + (long long)(m0 + lrow) * K + lcol * 4;
    const float* bgp = Bb + (long long)(n0 + lrow) * K + lcol * 4;
    const uint32_t adst0 = asb + (uint32_t)(lrow * PAD * 4 + lcol * 16);
    const uint32_t bdst0 = bsb + (uint32_t)(lrow * PAD * 4 + lcol * 16);
    const long long g32 = 32LL * K;       // 32-row step in floats

    auto load_stage = [&](int slot) {
        const uint32_t soA = (uint32_t)slot * (ASZ_F * 4);
        const uint32_t soB = (uint32_t)slot * (BSZ_F * 4);
        #pragma unroll
        for (int it = 0; it < 4; it++)
            cp16(adst0 + soA + (uint32_t)it * (32 * PAD * 4), agp + it * g32);
        #pragma unroll
        for (int it = 0; it < 4; it++)
            cp16(bdst0 + soB + (uint32_t)it * (32 * PAD * 4), bgp + it * g32);
        asm volatile("cp.async.commit_group;");
        agp += BK; bgp += BK;
    };

    // ---- per-thread fragment base addresses (all frag loads = base + imm) ----
    const uint32_t afrag0 = asb + (uint32_t)(((warp_m + lq) * PAD + 4 * lr) * 4);
    const uint32_t bfrag0 = bsb + (uint32_t)(((warp_n + lq) * PAD + 4 * lr) * 4);

    // prologue: preload first stage
    load_stage(0);

    for (int kt = 0; kt < KT; kt++) {
        asm volatile("cp.async.wait_group 0;");
        __syncthreads();

        if (kt + 1 < KT) load_stage((kt + 1) & 1);

        const uint32_t ab = afrag0 + (uint32_t)(kt & 1) * (ASZ_F * 4);
        const uint32_t bb = bfrag0 + (uint32_t)(kt & 1) * (BSZ_F * 4);

        #pragma unroll
        for (int p = 0; p < 2; p++) {          // two 16-k pairs per BK=32
            float4 alo[4], ahi[4], bv[4];
            #pragma unroll
            for (int mf = 0; mf < 4; mf++) {
                lds128(alo[mf], ab + (uint32_t)((mf * 16 * PAD + p * 16) * 4));
                lds128(ahi[mf], ab + (uint32_t)(((mf * 16 + 8) * PAD + p * 16) * 4));
            }
            #pragma unroll
            for (int nf = 0; nf < 4; nf++)
                lds128(bv[nf], bb + (uint32_t)((nf * 8 * PAD + p * 16) * 4));

            // group 0: phys k = 4lr, 4lr+1 (.x, .y)
            #pragma unroll
            for (int mf = 0; mf < 4; mf++)
                #pragma unroll
                for (int nf = 0; nf < 4; nf++)
                    mma4(acc[mf][nf], alo[mf].x, ahi[mf].x, alo[mf].y, ahi[mf].y,
                         bv[nf].x, bv[nf].y);
            // group 1: phys k = 4lr+2, 4lr+3 (.z, .w)
            #pragma unroll
            for (int mf = 0; mf < 4; mf++)
                #pragma unroll
                for (int nf = 0; nf < 4; nf++)
                    mma4(acc[mf][nf], alo[mf].z, ahi[mf].z, alo[mf].w, ahi[mf].w,
                         bv[nf].z, bv[nf].w);
        }
        __syncthreads();
    }

    // -------- epilogue: regs -> gmem (float2 stores; sectors fully covered) ----
    #pragma unroll
    for (int mf = 0; mf < 4; mf++) {
        const int row = m0 + warp_m + mf * 16 + lq;
        #pragma unroll
        for (int nf = 0; nf < 4; nf++) {
            const int col = n0 + warp_n + nf * 8 + 2 * lr;
            float b0 = 0.f, b1 = 0.f;
            if (bias) { b0 = __ldg(&bias[col]); b1 = __ldg(&bias[col + 1]); }
            float v0 = acc[mf][nf][0] + b0, v1 = acc[mf][nf][1] + b1;
            float v2 = acc[mf][nf][2] + b0, v3 = acc[mf][nf][3] + b1;
            if (Rb) {
                float2 r0 = *reinterpret_cast<const float2*>(&Rb[(long long)row * N + col]);
                float2 r1 = *reinterpret_cast<const float2*>(&Rb[(long long)(row + 8) * N + col]);
                v0 += r0.x; v1 += r0.y; v2 += r1.x; v3 += r1.y;
            }
            if (round_out) {
                v0 = rn_tf32(v0); v1 = rn_tf32(v1);
                v2 = rn_tf32(v2); v3 = rn_tf32(v3);
            }
            *reinterpret_cast<float2*>(&Cb[(long long)row * N + col])       = make_float2(v0, v1);
            *reinterpret_cast<float2*>(&Cb[(long long)(row + 8) * N + col]) = make_float2(v2, v3);
        }
    }
}

// ---------------- elementwise kernels ----------------
__global__ __launch_bounds__(256) void round_tf32_k(const float* __restrict__ a,
                                                    float* __restrict__ b, long long n4)
{
    long long i = ((long long)blockIdx.x * 256 + threadIdx.x);
    if (i >= n4) return;
    float4 v = reinterpret_cast<const float4*>(a)[i];
    v.x = rn_tf32(v.x); v.y = rn_tf32(v.y); v.z = rn_tf32(v.z); v.w = rn_tf32(v.w);
    reinterpret_cast<float4*>(b)[i] = v;
}

// round 4 weight matrices in one launch (blockIdx.y selects matrix)
__global__ __launch_bounds__(256) void round_w4_k(
    const float* __restrict__ w0, const float* __restrict__ w1,
    const float* __restrict__ w2, const float* __restrict__ w3,
    float* __restrict__ dst, long long n4)
{
    const float* srcs[4] = {w0, w1, w2, w3};
    const float* a = srcs[blockIdx.y];
    float* b = dst + (long long)blockIdx.y * (n4 * 4);
    long long i = ((long long)blockIdx.x * 256 + threadIdx.x);
    if (i >= n4) return;
    float4 v = reinterpret_cast<const float4*>(a)[i];
    v.x = rn_tf32(v.x); v.y = rn_tf32(v.y); v.z = rn_tf32(v.z); v.w = rn_tf32(v.w);
    reinterpret_cast<float4*>(b)[i] = v;
}

// single-pass register-resident softmax for rows of exactly 2048 cols.
// out = rn_tf32(softmax(scale * s)); one global read + one global write.
__global__ __launch_bounds__(256) void softmax2048(float* __restrict__ S, float scale)
{
    float* p = S + (long long)blockIdx.x * 2048;
    const int tid  = threadIdx.x;
    const int lane = tid & 31, wrp = tid >> 5;
    __shared__ float red[8];

    float4 v0 = *reinterpret_cast<const float4*>(p + tid * 4);
    float4 v1 = *reinterpret_cast<const float4*>(p + 1024 + tid * 4);

    float m = fmaxf(fmaxf(fmaxf(v0.x, v0.y), fmaxf(v0.z, v0.w)),
                    fmaxf(fmaxf(v1.x, v1.y), fmaxf(v1.z, v1.w)));
    #pragma unroll
    for (int o = 16; o > 0; o >>= 1) m = fmaxf(m, __shfl_xor_sync(0xffffffffu, m, o));
    if (lane == 0) red[wrp] = m;
    __syncthreads();
    m = red[lane & 7];
    #pragma unroll
    for (int o = 4; o > 0; o >>= 1) m = fmaxf(m, __shfl_xor_sync(0xffffffffu, m, o));

    v0.x = __expf((v0.x - m) * scale); v0.y = __expf((v0.y - m) * scale);
    v0.z = __expf((v0.z - m) * scale); v0.w = __expf((v0.w - m) * scale);
    v1.x = __expf((v1.x - m) * scale); v1.y = __expf((v1.y - m) * scale);
    v1.z = __expf((v1.z - m) * scale); v1.w = __expf((v1.w - m) * scale);

    float s = (v0.x + v0.y) + (v0.z + v0.w) + (v1.x + v1.y) + (v1.z + v1.w);
    #pragma unroll
    for (int o = 16; o > 0; o >>= 1) s += __shfl_xor_sync(0xffffffffu, s, o);
    __syncthreads();
    if (lane == 0) red[wrp] = s;
    __syncthreads();
    s = red[lane & 7];
    #pragma unroll
    for (int o = 4; o > 0; o >>= 1) s += __shfl_xor_sync(0xffffffffu, s, o);

    const float inv = 1.0f / s;
    v0.x = rn_tf32(v0.x * inv); v0.y = rn_tf32(v0.y * inv);
    v0.z = rn_tf32(v0.z * inv); v0.w = rn_tf32(v0.w * inv);
    v1.x = rn_tf32(v1.x * inv); v1.y = rn_tf32(v1.y * inv);
    v1.z = rn_tf32(v1.z * inv); v1.w = rn_tf32(v1.w * inv);
    *reinterpret_cast<float4*>(p + tid * 4) = v0;
    *reinterpret_cast<float4*>(p + 1024 + tid * 4) = v1;
}

// ---------------- host launcher ----------------
extern "C" void kernel_launch(void* const* d_in, const int* in_sizes, int n_in,
                              void* d_out, int out_size)
{
    const float* x  = (const float*)d_in[0];
    const float* ce = (const float*)d_in[1];
    const float* Wq = (const float*)d_in[2];
    const float* bq = (const float*)d_in[3];
    const float* Wk = (const float*)d_in[4];
    const float* bk = (const float*)d_in[5];
    const float* Wv = (const float*)d_in[6];
    const float* bv = (const float*)d_in[7];
    const float* Wo = (const float*)d_in[8];
    const float* bo = (const float*)d_in[9];
    float* out = (float*)d_out;

    float *Q, *Kb, *Vt, *S, *XR, *CR, *WR;
    cudaGetSymbolAddress((void**)&Q,  g_Q);
    cudaGetSymbolAddress((void**)&Kb, g_Kb);
    cudaGetSymbolAddress((void**)&Vt, g_Vt);
    cudaGetSymbolAddress((void**)&S,  g_S);
    cudaGetSymbolAddress((void**)&XR, g_XR);
    cudaGetSymbolAddress((void**)&CR, g_CR);
    cudaGetSymbolAddress((void**)&WR, g_WR);
    float* WRq = WR + 0 * CH * CH;
    float* WRk = WR + 1 * CH * CH;
    float* WRv = WR + 2 * CH * CH;
    float* WRo = WR + 3 * CH * CH;

    const int SMEMB = 2 * (ASZ_F + BSZ_F) * 4;   // 98304 B -> 2 CTAs/SM
    cudaFuncSetAttribute(gemm_tf32, cudaFuncAttributeMaxDynamicSharedMemorySize, SMEMB);

    const long long NX4 = (long long)BATCH * SEQ * CH / 4;
    const long long NW4 = (long long)CH * CH / 4;
    dim3 t(256), tg(NTHR);

    // RN-round all MMA operand sources (zero-mean tf32 error)
    round_tf32_k<<<(unsigned)((NX4 + 255) / 256), t>>>(x,  XR, NX4);
    round_tf32_k<<<(unsigned)((NX4 + 255) / 256), t>>>(ce, CR, NX4);
    round_w4_k<<<dim3((unsigned)((NW4 + 255) / 256), 4), t>>>(Wq, Wk, Wv, Wo, WR, NW4);

    const int M = BATCH * SEQ;  // 8192

    // Q = x@Wq^T + bq (rounded);  K = ce@Wk^T + bk (rounded)
    gemm_tf32<<<dim3(CH / BN, M / BM, 1), tg, SMEMB>>>(
        XR, WRq, bq, nullptr, Q,  M, CH, CH, 0, 0, 0, 1);
    gemm_tf32<<<dim3(CH / BN, M / BM, 1), tg, SMEMB>>>(
        CR, WRk, bk, nullptr, Kb, M, CH, CH, 0, 0, 0, 1);

    // Vt_b[c, s] = sum_k Wv[c,k] * ce_b[s,k]  (rounded; no bias)
    gemm_tf32<<<dim3(SEQ / BN, CH / BM, BATCH), tg, SMEMB>>>(
        WRv, CR, nullptr, nullptr, Vt, CH, SEQ, CH,
        0, (long long)SEQ * CH, (long long)CH * SEQ, 1);

    // S_b = Q_b @ K_b^T (raw scores, fp32)
    gemm_tf32<<<dim3(SEQ / BN, SEQ / BM, BATCH), tg, SMEMB>>>(
        Q, Kb, nullptr, nullptr, S, SEQ, SEQ, CH,
        (long long)SEQ * CH, (long long)SEQ * CH, (long long)SEQ * SEQ, 0);

    // P = rn_tf32(softmax(scale * S)) — single pass, register resident
    softmax2048<<<BATCH * SEQ, t>>>(S, 0.03125f);

    // XR_b = rn_tf32(x_b + P_b @ Vt_b^T + bv)  — residual fused into epilogue
    // (bias fold exact: rows of P sum to 1)
    gemm_tf32<<<dim3(CH / BN, SEQ / BM, BATCH), tg, SMEMB>>>(
        S, Vt, bv, x, XR, SEQ, CH, SEQ,
        (long long)SEQ * SEQ, (long long)CH * SEQ, (long long)SEQ * CH, 1);

    // out = (x+At) @ Wo^T + bo (full fp32 output)
    gemm_tf32<<<dim3(CH / BN, M / BM, 1), tg, SMEMB>>>(
        XR, WRo, bo, nullptr, out, M, CH, CH, 0, 0, 0, 0);
}

// round 15
// speedup vs baseline: 1.0638x; 1.0638x over previous
#include <cuda_runtime.h>
#include <cstdint>

#define BATCH 4
#define SEQ   2048
#define CH    1024

#define BM 128
#define BN 64
#define BK 32
#define NTHR 256
#define PAD 40              // floats per smem row (32 data + 8 pad) -> conflict-free float2 frags
#define ASZ_F (BM * PAD)    // 5120 floats per A stage
#define BSZ_F (BN * PAD)    // 2560 floats per B stage

// ---------------- scratch (device globals; allocation-free) ----------------
__device__ float g_Q [BATCH*SEQ*CH];            // 32 MB (tf32-rounded Q)
__device__ float g_Kb[BATCH*SEQ*CH];            // 32 MB (tf32-rounded K)
__device__ float g_Vt[BATCH*SEQ*CH];            // 32 MB (V^T per batch [CH, SEQ], rounded)
__device__ float g_S [(size_t)BATCH*SEQ*SEQ];   // 64 MB scores / probs
__device__ float g_XR[BATCH*SEQ*CH];            // 32 MB rounded x (later rounded residual)
__device__ float g_CR[BATCH*SEQ*CH];            // 32 MB rounded content_embeddings
__device__ float g_WR[4*CH*CH];                 // 16 MB rounded Wq,Wk,Wv,Wo

// ---------------- helpers ----------------
__device__ __forceinline__ uint32_t smem_u32(const void* p){
    uint32_t a;
    asm("{ .reg .u64 t; cvta.to.shared.u64 t, %1; cvt.u32.u64 %0, t; }" : "=r"(a) : "l"(p));
    return a;
}
__device__ __forceinline__ void cp16(uint32_t dst, const void* src){
    asm volatile("cp.async.cg.shared.global [%0], [%1], 16;" :: "r"(dst), "l"(src));
}
__device__ __forceinline__ void lds64(float& x, float& y, uint32_t a){
    asm volatile("ld.shared.v2.f32 {%0,%1}, [%2];" : "=f"(x), "=f"(y) : "r"(a));
}
__device__ __forceinline__ float rn_tf32(float x){
    uint32_t u; asm("cvt.rna.tf32.f32 %0, %1;" : "=r"(u) : "f"(x));
    return __uint_as_float(u);
}
__device__ __forceinline__ void mma_tf32(float* d, const float* a, const float* b){
    asm volatile(
        "mma.sync.aligned.m16n8k8.row.col.f32.tf32.tf32.f32 "
        "{%0,%1,%2,%3}, {%4,%5,%6,%7}, {%8,%9}, {%0,%1,%2,%3};"
        : "+f"(d[0]), "+f"(d[1]), "+f"(d[2]), "+f"(d[3])
        : "r"(__float_as_uint(a[0])), "r"(__float_as_uint(a[1])),
          "r"(__float_as_uint(a[2])), "r"(__float_as_uint(a[3])),
          "r"(__float_as_uint(b[0])), "r"(__float_as_uint(b[1])));
}

// ---------------- tf32 tensor-core NT GEMM ----------------
// C[m,n] = sum_k A[m,k]*B[n,k] (+ bias[n]) (+ resid[m,n]); A:[M,K], B:[N,K] row-major.
// 128x64 block tile, 32x32 warp tiles (8 warps, 4x2), BK=32, 2-stage cp.async,
// 3 CTAs per SM (small acc -> register slack lets ptxas software-pipeline
// fragment loads across 8-k groups; 6 warps/SMSP hide LDS latency).
// Fragment k-slots permuted (slot lr <-> k=2lr, slot lr+4 <-> k=2lr+1): each
// thread's two k-values are adjacent -> one LDS.64 per fragment pair; the
// contraction is order-invariant within each 8-k group, so results are identical.
__global__ __launch_bounds__(NTHR, 3) void gemm_tf32(
    const float* __restrict__ A, const float* __restrict__ Bm,
    const float* __restrict__ bias, const float* __restrict__ Rm,
    float* __restrict__ Cm,
    int M, int N, int K,
    long long az, long long bz, long long cz, int round_out)
{
    extern __shared__ float sm[];
    const uint32_t asb = smem_u32(sm);                 // A stages: [2][BM][PAD]
    const uint32_t bsb = asb + 2 * ASZ_F * 4;          // B stages: [2][BN][PAD]

    const int tid  = threadIdx.x;
    const int wid  = tid >> 5;
    const int lane = tid & 31;
    const int lq   = lane >> 2;   // 0..7
    const int lr   = lane & 3;    // 0..3

    const int z = blockIdx.z;
    const float* Ab = A  + (long long)z * az;
    const float* Bb = Bm + (long long)z * bz;
    float*       Cb = Cm + (long long)z * cz;
    const float* Rb = Rm ? (Rm + (long long)z * cz) : nullptr;
    const int m0 = blockIdx.y * BM;
    const int n0 = blockIdx.x * BN;
    const int KT = K / BK;

    const int warp_m = (wid & 3) * 32;    // 4 warps along M
    const int warp_n = (wid >> 2) * 32;   // 2 warps along N

    float acc[2][4][4];
    #pragma unroll
    for (int i = 0; i < 2; i++)
        #pragma unroll
        for (int j = 0; j < 4; j++)
            #pragma unroll
            for (int r = 0; r < 4; r++) acc[i][j][r] = 0.0f;

    // ---- persistent loader state: A = 1024 16B-chunks (4/thread),
    //      B = 512 chunks (2/thread); rows lrow + it*32, advanced BK/stage ----
    const int lrow = tid >> 3, lcol = tid & 7;
    const float* agp = Ab + (long long)(m0 + lrow) * K + lcol * 4;
    const float* bgp = Bb + (long long)(n0 + lrow) * K + lcol * 4;
    const uint32_t adst0 = asb + (uint32_t)(lrow * PAD * 4 + lcol * 16);
    const uint32_t bdst0 = bsb + (uint32_t)(lrow * PAD * 4 + lcol * 16);
    const long long g32 = 32LL * K;       // 32-row step in floats

    auto load_stage = [&](int slot) {
        const uint32_t soA = (uint32_t)slot * (ASZ_F * 4);
        const uint32_t soB = (uint32_t)slot * (BSZ_F * 4);
        #pragma unroll
        for (int it = 0; it < 4; it++)
            cp16(adst0 + soA + (uint32_t)it * (32 * PAD * 4), agp + it * g32);
        #pragma unroll
        for (int it = 0; it < 2; it++)
            cp16(bdst0 + soB + (uint32_t)it * (32 * PAD * 4), bgp + it * g32);
        asm volatile("cp.async.commit_group;");
        agp += BK; bgp += BK;
    };

    // ---- per-thread fragment base addresses (all frag loads = base + imm) ----
    const uint32_t afrag0 = asb + (uint32_t)(((warp_m + lq) * PAD + 2 * lr) * 4);
    const uint32_t bfrag0 = bsb + (uint32_t)(((warp_n + lq) * PAD + 2 * lr) * 4);

    // prologue: preload first stage
    load_stage(0);

    for (int kt = 0; kt < KT; kt++) {
        asm volatile("cp.async.wait_group 0;");
        __syncthreads();

        if (kt + 1 < KT) load_stage((kt + 1) & 1);

        const uint32_t ab = afrag0 + (uint32_t)(kt & 1) * (ASZ_F * 4);
        const uint32_t bb = bfrag0 + (uint32_t)(kt & 1) * (BSZ_F * 4);

        #pragma unroll
        for (int g = 0; g < 4; g++) {
            const int ks = g * 8;
            float af[2][4], bf[4][2];
            #pragma unroll
            for (int mf = 0; mf < 2; mf++) {
                lds64(af[mf][0], af[mf][2], ab + (uint32_t)((mf * 16 * PAD + ks) * 4));
                lds64(af[mf][1], af[mf][3], ab + (uint32_t)(((mf * 16 + 8) * PAD + ks) * 4));
            }
            #pragma unroll
            for (int nf = 0; nf < 4; nf++)
                lds64(bf[nf][0], bf[nf][1], bb + (uint32_t)((nf * 8 * PAD + ks) * 4));
            #pragma unroll
            for (int mf = 0; mf < 2; mf++)
                #pragma unroll
                for (int nf = 0; nf < 4; nf++)
                    mma_tf32(acc[mf][nf], af[mf], bf[nf]);
        }
        __syncthreads();
    }

    // -------- epilogue: regs -> gmem (float2 stores; sectors fully covered) ----
    #pragma unroll
    for (int mf = 0; mf < 2; mf++) {
        const int row = m0 + warp_m + mf * 16 + lq;
        #pragma unroll
        for (int nf = 0; nf < 4; nf++) {
            const int col = n0 + warp_n + nf * 8 + 2 * lr;
            float b0 = 0.f, b1 = 0.f;
            if (bias) { b0 = __ldg(&bias[col]); b1 = __ldg(&bias[col + 1]); }
            float v0 = acc[mf][nf][0] + b0, v1 = acc[mf][nf][1] + b1;
            float v2 = acc[mf][nf][2] + b0, v3 = acc[mf][nf][3] + b1;
            if (Rb) {
                float2 r0 = *reinterpret_cast<const float2*>(&Rb[(long long)row * N + col]);
                float2 r1 = *reinterpret_cast<const float2*>(&Rb[(long long)(row + 8) * N + col]);
                v0 += r0.x; v1 += r0.y; v2 += r1.x; v3 += r1.y;
            }
            if (round_out) {
                v0 = rn_tf32(v0); v1 = rn_tf32(v1);
                v2 = rn_tf32(v2); v3 = rn_tf32(v3);
            }
            *reinterpret_cast<float2*>(&Cb[(long long)row * N + col])       = make_float2(v0, v1);
            *reinterpret_cast<float2*>(&Cb[(long long)(row + 8) * N + col]) = make_float2(v2, v3);
        }
    }
}

// ---------------- elementwise kernels ----------------
__global__ __launch_bounds__(256) void round_tf32_k(const float* __restrict__ a,
                                                    float* __restrict__ b, long long n4)
{
    long long i = ((long long)blockIdx.x * 256 + threadIdx.x);
    if (i >= n4) return;
    float4 v = reinterpret_cast<const float4*>(a)[i];
    v.x = rn_tf32(v.x); v.y = rn_tf32(v.y); v.z = rn_tf32(v.z); v.w = rn_tf32(v.w);
    reinterpret_cast<float4*>(b)[i] = v;
}

// round 4 weight matrices in one launch (blockIdx.y selects matrix)
__global__ __launch_bounds__(256) void round_w4_k(
    const float* __restrict__ w0, const float* __restrict__ w1,
    const float* __restrict__ w2, const float* __restrict__ w3,
    float* __restrict__ dst, long long n4)
{
    const float* srcs[4] = {w0, w1, w2, w3};
    const float* a = srcs[blockIdx.y];
    float* b = dst + (long long)blockIdx.y * (n4 * 4);
    long long i = ((long long)blockIdx.x * 256 + threadIdx.x);
    if (i >= n4) return;
    float4 v = reinterpret_cast<const float4*>(a)[i];
    v.x = rn_tf32(v.x); v.y = rn_tf32(v.y); v.z = rn_tf32(v.z); v.w = rn_tf32(v.w);
    reinterpret_cast<float4*>(b)[i] = v;
}

// single-pass register-resident softmax for rows of exactly 2048 cols.
// out = rn_tf32(softmax(scale * s)); one global read + one global write.
__global__ __launch_bounds__(256) void softmax2048(float* __restrict__ S, float scale)
{
    float* p = S + (long long)blockIdx.x * 2048;
    const int tid  = threadIdx.x;
    const int lane = tid & 31, wrp = tid >> 5;
    __shared__ float red[8];

    float4 v0 = *reinterpret_cast<const float4*>(p + tid * 4);
    float4 v1 = *reinterpret_cast<const float4*>(p + 1024 + tid * 4);

    float m = fmaxf(fmaxf(fmaxf(v0.x, v0.y), fmaxf(v0.z, v0.w)),
                    fmaxf(fmaxf(v1.x, v1.y), fmaxf(v1.z, v1.w)));
    #pragma unroll
    for (int o = 16; o > 0; o >>= 1) m = fmaxf(m, __shfl_xor_sync(0xffffffffu, m, o));
    if (lane == 0) red[wrp] = m;
    __syncthreads();
    m = red[lane & 7];
    #pragma unroll
    for (int o = 4; o > 0; o >>= 1) m = fmaxf(m, __shfl_xor_sync(0xffffffffu, m, o));

    v0.x = __expf((v0.x - m) * scale); v0.y = __expf((v0.y - m) * scale);
    v0.z = __expf((v0.z - m) * scale); v0.w = __expf((v0.w - m) * scale);
    v1.x = __expf((v1.x - m) * scale); v1.y = __expf((v1.y - m) * scale);
    v1.z = __expf((v1.z - m) * scale); v1.w = __expf((v1.w - m) * scale);

    float s = (v0.x + v0.y) + (v0.z + v0.w) + (v1.x + v1.y) + (v1.z + v1.w);
    #pragma unroll
    for (int o = 16; o > 0; o >>= 1) s += __shfl_xor_sync(0xffffffffu, s, o);
    __syncthreads();
    if (lane == 0) red[wrp] = s;
    __syncthreads();
    s = red[lane & 7];
    #pragma unroll
    for (int o = 4; o > 0; o >>= 1) s += __shfl_xor_sync(0xffffffffu, s, o);

    const float inv = 1.0f / s;
    v0.x = rn_tf32(v0.x * inv); v0.y = rn_tf32(v0.y * inv);
    v0.z = rn_tf32(v0.z * inv); v0.w = rn_tf32(v0.w * inv);
    v1.x = rn_tf32(v1.x * inv); v1.y = rn_tf32(v1.y * inv);
    v1.z = rn_tf32(v1.z * inv); v1.w = rn_tf32(v1.w * inv);
    *reinterpret_cast<float4*>(p + tid * 4) = v0;
    *reinterpret_cast<float4*>(p + 1024 + tid * 4) = v1;
}

// ---------------- host launcher ----------------
extern "C" void kernel_launch(void* const* d_in, const int* in_sizes, int n_in,
                              void* d_out, int out_size)
{
    const float* x  = (const float*)d_in[0];
    const float* ce = (const float*)d_in[1];
    const float* Wq = (const float*)d_in[2];
    const float* bq = (const float*)d_in[3];
    const float* Wk = (const float*)d_in[4];
    const float* bk = (const float*)d_in[5];
    const float* Wv = (const float*)d_in[6];
    const float* bv = (const float*)d_in[7];
    const float* Wo = (const float*)d_in[8];
    const float* bo = (const float*)d_in[9];
    float* out = (float*)d_out;

    float *Q, *Kb, *Vt, *S, *XR, *CR, *WR;
    cudaGetSymbolAddress((void**)&Q,  g_Q);
    cudaGetSymbolAddress((void**)&Kb, g_Kb);
    cudaGetSymbolAddress((void**)&Vt, g_Vt);
    cudaGetSymbolAddress((void**)&S,  g_S);
    cudaGetSymbolAddress((void**)&XR, g_XR);
    cudaGetSymbolAddress((void**)&CR, g_CR);
    cudaGetSymbolAddress((void**)&WR, g_WR);
    float* WRq = WR + 0 * CH * CH;
    float* WRk = WR + 1 * CH * CH;
    float* WRv = WR + 2 * CH * CH;
    float* WRo = WR + 3 * CH * CH;

    const int SMEMB = 2 * (ASZ_F + BSZ_F) * 4;   // 61440 B -> 3 CTAs/SM
    cudaFuncSetAttribute(gemm_tf32, cudaFuncAttributeMaxDynamicSharedMemorySize, SMEMB);

    const long long NX4 = (long long)BATCH * SEQ * CH / 4;
    const long long NW4 = (long long)CH * CH / 4;
    dim3 t(256), tg(NTHR);

    // RN-round all MMA operand sources (zero-mean tf32 error)
    round_tf32_k<<<(unsigned)((NX4 + 255) / 256), t>>>(x,  XR, NX4);
    round_tf32_k<<<(unsigned)((NX4 + 255) / 256), t>>>(ce, CR, NX4);
    round_w4_k<<<dim3((unsigned)((NW4 + 255) / 256), 4), t>>>(Wq, Wk, Wv, Wo, WR, NW4);

    const int M = BATCH * SEQ;  // 8192

    // Q = x@Wq^T + bq (rounded);  K = ce@Wk^T + bk (rounded)
    gemm_tf32<<<dim3(CH / BN, M / BM, 1), tg, SMEMB>>>(
        XR, WRq, bq, nullptr, Q,  M, CH, CH, 0, 0, 0, 1);
    gemm_tf32<<<dim3(CH / BN, M / BM, 1), tg, SMEMB>>>(
        CR, WRk, bk, nullptr, Kb, M, CH, CH, 0, 0, 0, 1);

    // Vt_b[c, s] = sum_k Wv[c,k] * ce_b[s,k]  (rounded; no bias)
    gemm_tf32<<<dim3(SEQ / BN, CH / BM, BATCH), tg, SMEMB>>>(
        WRv, CR, nullptr, nullptr, Vt, CH, SEQ, CH,
        0, (long long)SEQ * CH, (long long)CH * SEQ, 1);

    // S_b = Q_b @ K_b^T (raw scores, fp32)
    gemm_tf32<<<dim3(SEQ / BN, SEQ / BM, BATCH), tg, SMEMB>>>(
        Q, Kb, nullptr, nullptr, S, SEQ, SEQ, CH,
        (long long)SEQ * CH, (long long)SEQ * CH, (long long)SEQ * SEQ, 0);

    // P = rn_tf32(softmax(scale * S)) — single pass, register resident
    softmax2048<<<BATCH * SEQ, t>>>(S, 0.03125f);

    // XR_b = rn_tf32(x_b + P_b @ Vt_b^T + bv)  — residual fused into epilogue
    // (bias fold exact: rows of P sum to 1)
    gemm_tf32<<<dim3(CH / BN, SEQ / BM, BATCH), tg, SMEMB>>>(
        S, Vt, bv, x, XR, SEQ, CH, SEQ,
        (long long)SEQ * SEQ, (long long)CH * SEQ, (long long)SEQ * CH, 1);

    // out = (x+At) @ Wo^T + bo (full fp32 output)
    gemm_tf32<<<dim3(CH / BN, M / BM, 1), tg, SMEMB>>>(
        XR, WRo, bo, nullptr, out, M, CH, CH, 0, 0, 0, 0);
}